// round 10
// baseline (speedup 1.0000x reference)
#include <cuda_runtime.h>

// Problem constants (fixed by the dataset)
#define BS 8
#define NQ 1500
#define NPRED (BS * NQ)   // 12000
#define NTGT 4800
#define BJ 256            // targets per block tile (32 lanes x 8 j)
#define PRW 12            // preds per warp
#define BI (8 * PRW)      // 96 preds per block; 12000 % 96 == 0

// C[i,j] = 5*|px_i - tx_j| + 5*|py_i - ty_j| + sp_i - t0_j*x0_i - t1_j*x1_i
// sp_i = softplus(x0_i) + softplus(x1_i)

union F4 {
    float4 f;
    unsigned long long u[2];   // u[0] = {f.x, f.y}, u[1] = {f.z, f.w}
};

__device__ __forceinline__ unsigned long long fma2(unsigned long long a,
                                                   unsigned long long b,
                                                   unsigned long long c)
{
    unsigned long long d;
    asm("fma.rn.f32x2 %0, %1, %2, %3;" : "=l"(d) : "l"(a), "l"(b), "l"(c));
    return d;
}

// 256-bit streaming store (sm_100+)
__device__ __forceinline__ void st_cs_v8(float* p, const float4& a, const float4& b)
{
    asm volatile("st.global.cs.v8.f32 [%0], {%1,%2,%3,%4,%5,%6,%7,%8};"
                 :: "l"(p),
                    "f"(a.x), "f"(a.y), "f"(a.z), "f"(a.w),
                    "f"(b.x), "f"(b.y), "f"(b.z), "f"(b.w)
                 : "memory");
}

__global__ __launch_bounds__(256)
void hungarian_cost_kernel(const float* __restrict__ pred_logits,
                           const float* __restrict__ pred_points,
                           const float* __restrict__ tgt_labels,
                           const float* __restrict__ tgt_points,
                           float* __restrict__ out)
{
    __shared__ float  s_tx[BJ], s_ty[BJ];   // 5*tx, 5*ty
    __shared__ float  s_t0[BJ], s_t1[BJ];   // -t0, -t1 (negated at staging)
    __shared__ float4 s_ps[BI];             // {5*px, 5*py, sp, sp}
    __shared__ float4 s_ex[BI];             // {x0, x0, x1, x1}

    const int lane   = threadIdx.x;
    const int w      = threadIdx.y;          // warp id 0..7
    const int tid    = w * 32 + lane;
    const int j_base = blockIdx.x * BJ;
    const int i_base = blockIdx.y * BI;

    // ---- Prologue: stage 256 targets (all threads) + 96 preds (first 96) ----
    {
        const int jt = j_base + tid;
        float2 p = make_float2(0.f, 0.f), l2 = make_float2(0.f, 0.f);
        if (jt < NTGT) {
            p  = ((const float2*)tgt_points)[jt];
            l2 = ((const float2*)tgt_labels)[jt];
        }
        s_tx[tid] = 5.0f * p.x;
        s_ty[tid] = 5.0f * p.y;
        s_t0[tid] = -l2.x;
        s_t1[tid] = -l2.y;
    }
    if (tid < BI) {
        const int i = i_base + tid;          // always < NPRED (12000 % 96 == 0)
        const float2 x = ((const float2*)pred_logits)[i];
        const float2 p = ((const float2*)pred_points)[i];
        const float sp = fmaxf(x.x, 0.f) + log1pf(expf(-fabsf(x.x)))
                       + fmaxf(x.y, 0.f) + log1pf(expf(-fabsf(x.y)));
        s_ps[tid] = make_float4(5.0f * p.x, 5.0f * p.y, sp, sp);
        s_ex[tid] = make_float4(x.x, x.x, x.y, x.y);
    }

    __syncthreads();

    const int j0 = j_base + lane * 8;
    if (j0 >= NTGT) return;   // last tile: 4800-4608=192 -> lanes 0..23 active

    // ---- Hoist this lane's 8 targets (2x float4 per SoA array) ----
    F4 vtxA, vtyA, vt0A, vt1A, vtxB, vtyB, vt0B, vt1B;
    vtxA.f = ((const float4*)s_tx)[2 * lane];
    vtxB.f = ((const float4*)s_tx)[2 * lane + 1];
    vtyA.f = ((const float4*)s_ty)[2 * lane];
    vtyB.f = ((const float4*)s_ty)[2 * lane + 1];
    vt0A.f = ((const float4*)s_t0)[2 * lane];
    vt0B.f = ((const float4*)s_t0)[2 * lane + 1];
    vt1A.f = ((const float4*)s_t1)[2 * lane];
    vt1B.f = ((const float4*)s_t1)[2 * lane + 1];

    float* const obase = out + (size_t)(i_base + w * PRW) * NTGT + j0;

    // ---- Main loop: 12 preds per warp, one 256-bit store per pred ----
    #pragma unroll
    for (int pl = 0; pl < PRW; pl++) {
        F4 ps, ex;
        ps.f = s_ps[w * PRW + pl];   // broadcast LDS.128: {5px,5py,sp,sp}
        ex.f = s_ex[w * PRW + pl];   // broadcast LDS.128: {x0,x0,x1,x1}

        const float px = ps.f.x;
        const float py = ps.f.y;
        const unsigned long long sp2 = ps.u[1];
        const unsigned long long x02 = ex.u[0];
        const unsigned long long x12 = ex.u[1];

        // classification term, packed: e = sp - t0*x0 - t1*x1
        F4 eA, eB;
        eA.u[0] = fma2(vt0A.u[0], x02, fma2(vt1A.u[0], x12, sp2));
        eA.u[1] = fma2(vt0A.u[1], x02, fma2(vt1A.u[1], x12, sp2));
        eB.u[0] = fma2(vt0B.u[0], x02, fma2(vt1B.u[0], x12, sp2));
        eB.u[1] = fma2(vt0B.u[1], x02, fma2(vt1B.u[1], x12, sp2));

        // point term, scalar (abs is a free FADD input modifier)
        float4 rA, rB;
        rA.x = (fabsf(px - vtxA.f.x) + fabsf(py - vtyA.f.x)) + eA.f.x;
        rA.y = (fabsf(px - vtxA.f.y) + fabsf(py - vtyA.f.y)) + eA.f.y;
        rA.z = (fabsf(px - vtxA.f.z) + fabsf(py - vtyA.f.z)) + eA.f.z;
        rA.w = (fabsf(px - vtxA.f.w) + fabsf(py - vtyA.f.w)) + eA.f.w;
        rB.x = (fabsf(px - vtxB.f.x) + fabsf(py - vtyB.f.x)) + eB.f.x;
        rB.y = (fabsf(px - vtxB.f.y) + fabsf(py - vtyB.f.y)) + eB.f.y;
        rB.z = (fabsf(px - vtxB.f.z) + fabsf(py - vtyB.f.z)) + eB.f.z;
        rB.w = (fabsf(px - vtxB.f.w) + fabsf(py - vtyB.f.w)) + eB.f.w;

        st_cs_v8(obase + (size_t)pl * NTGT, rA, rB);   // 1024B/warp, coalesced
    }
}

extern "C" void kernel_launch(void* const* d_in, const int* in_sizes, int n_in,
                              void* d_out, int out_size)
{
    const float* pred_logits = (const float*)d_in[0];  // (8,1500,2)
    const float* pred_points = (const float*)d_in[1];  // (8,1500,2)
    const float* tgt_labels  = (const float*)d_in[2];  // (4800,2)
    const float* tgt_points  = (const float*)d_in[3];  // (4800,2)
    float* out = (float*)d_out;                        // (8,1500,4800)

    dim3 block(32, 8);
    dim3 grid((NTGT + BJ - 1) / BJ, NPRED / BI);       // (19, 125)
    hungarian_cost_kernel<<<grid, block>>>(pred_logits, pred_points,
                                           tgt_labels, tgt_points, out);
}

// round 12
// speedup vs baseline: 1.0580x; 1.0580x over previous
#include <cuda_runtime.h>

// Problem constants (fixed by the dataset)
#define BS 8
#define NQ 1500
#define NPRED (BS * NQ)   // 12000
#define NTGT 4800
#define BJ 128            // targets per block tile (32 lanes x 4 j)
#define PRW 12            // preds per warp
#define BI (8 * PRW)      // 96 preds per block; 12000 % 96 == 0
#define EL_LIMIT 4992     // preds whose output rows are L2-pinned (~95.8 MB)

// C[i,j] = 5*|px_i - tx_j| + 5*|py_i - ty_j| + sp_i - t0_j*x0_i - t1_j*x1_i
// sp_i = softplus(x0_i) + softplus(x1_i)

__device__ __forceinline__ unsigned long long mk_evict_last_policy()
{
    unsigned long long pol;
    asm("createpolicy.fractional.L2::evict_last.b64 %0, 1.0;" : "=l"(pol));
    return pol;
}

__device__ __forceinline__ void st_hint(float* p, const float4& v,
                                        unsigned long long pol)
{
    asm volatile("st.global.L2::cache_hint.v4.f32 [%0], {%1,%2,%3,%4}, %5;"
                 :: "l"(p), "f"(v.x), "f"(v.y), "f"(v.z), "f"(v.w), "l"(pol)
                 : "memory");
}

__global__ __launch_bounds__(256, 6)
void hungarian_cost_kernel(const float* __restrict__ pred_logits,
                           const float* __restrict__ pred_points,
                           const float* __restrict__ tgt_labels,
                           const float* __restrict__ tgt_points,
                           float* __restrict__ out)
{
    __shared__ float  s_tx[BJ], s_ty[BJ], s_t0[BJ], s_t1[BJ];  // target SoA (scaled)
    __shared__ float4 s_pred[BI];   // {5*px, 5*py, x0, x1}
    __shared__ float  s_sp[BI];     // softplus sum

    const int lane   = threadIdx.x;
    const int w      = threadIdx.y;          // warp id 0..7
    const int tid    = w * 32 + lane;
    const int j_base = blockIdx.x * BJ;
    const int i_base = blockIdx.y * BI;

    // ---- Prologue (disjoint thread ranges, single pass) ----
    if (tid < BJ) {
        const int jt = j_base + tid;
        float2 p = make_float2(0.f, 0.f), l2 = make_float2(0.f, 0.f);
        if (jt < NTGT) {
            p  = ((const float2*)tgt_points)[jt];
            l2 = ((const float2*)tgt_labels)[jt];
        }
        s_tx[tid] = 5.0f * p.x;
        s_ty[tid] = 5.0f * p.y;
        s_t0[tid] = l2.x;
        s_t1[tid] = l2.y;
    } else if (tid < BJ + BI) {
        const int i = i_base + (tid - BJ);   // always < NPRED
        const float2 x = ((const float2*)pred_logits)[i];
        const float2 p = ((const float2*)pred_points)[i];
        const float sp = fmaxf(x.x, 0.f) + log1pf(expf(-fabsf(x.x)))
                       + fmaxf(x.y, 0.f) + log1pf(expf(-fabsf(x.y)));
        s_pred[tid - BJ] = make_float4(5.0f * p.x, 5.0f * p.y, x.x, x.y);
        s_sp[tid - BJ]   = sp;
    }

    __syncthreads();

    const int j0 = j_base + lane * 4;
    if (j0 >= NTGT) return;   // partial last j-tile (4800 % 128 = 64)

    // ---- Hoist this lane's 4 targets: conflict-free LDS.128 from SoA ----
    const float4 vtx = ((const float4*)s_tx)[lane];
    const float4 vty = ((const float4*)s_ty)[lane];
    const float4 vt0 = ((const float4*)s_t0)[lane];
    const float4 vt1 = ((const float4*)s_t1)[lane];

    float* const obase = out + (size_t)(i_base + w * PRW) * NTGT + j0;
    const bool pin_l2 = (i_base < EL_LIMIT);            // uniform per block
    const unsigned long long pol = mk_evict_last_policy();

    // ---- Main loop: 12 preds per warp, broadcast pred state ----
    #pragma unroll
    for (int p4 = 0; p4 < PRW / 4; p4++) {
        const float4 sp4 = ((const float4*)s_sp)[w * (PRW / 4) + p4];  // broadcast
        #pragma unroll
        for (int q = 0; q < 4; q++) {
            const int    pl = p4 * 4 + q;
            const float4 pr = s_pred[w * PRW + pl];       // broadcast LDS.128
            const float  sp = (q == 0) ? sp4.x : (q == 1) ? sp4.y
                            : (q == 2) ? sp4.z : sp4.w;

            float4 r;
            {
                const float s = fabsf(pr.x - vtx.x) + fabsf(pr.y - vty.x);
                float e = fmaf(-vt0.x, pr.z, sp);
                e       = fmaf(-vt1.x, pr.w, e);
                r.x = s + e;
            }
            {
                const float s = fabsf(pr.x - vtx.y) + fabsf(pr.y - vty.y);
                float e = fmaf(-vt0.y, pr.z, sp);
                e       = fmaf(-vt1.y, pr.w, e);
                r.y = s + e;
            }
            {
                const float s = fabsf(pr.x - vtx.z) + fabsf(pr.y - vty.z);
                float e = fmaf(-vt0.z, pr.z, sp);
                e       = fmaf(-vt1.z, pr.w, e);
                r.z = s + e;
            }
            {
                const float s = fabsf(pr.x - vtx.w) + fabsf(pr.y - vty.w);
                float e = fmaf(-vt0.w, pr.z, sp);
                e       = fmaf(-vt1.w, pr.w, e);
                r.w = s + e;
            }

            float* const op = obase + (size_t)pl * NTGT;
            if (pin_l2) st_hint(op, r, pol);     // evict_last: stay dirty-resident in L2
            else        __stcs((float4*)op, r);  // evict-first: can't displace pinned set
        }
    }
}

extern "C" void kernel_launch(void* const* d_in, const int* in_sizes, int n_in,
                              void* d_out, int out_size)
{
    const float* pred_logits = (const float*)d_in[0];  // (8,1500,2)
    const float* pred_points = (const float*)d_in[1];  // (8,1500,2)
    const float* tgt_labels  = (const float*)d_in[2];  // (4800,2)
    const float* tgt_points  = (const float*)d_in[3];  // (4800,2)
    float* out = (float*)d_out;                        // (8,1500,4800)

    dim3 block(32, 8);
    dim3 grid((NTGT + BJ - 1) / BJ, NPRED / BI);       // (38, 125)
    hungarian_cost_kernel<<<grid, block>>>(pred_logits, pred_points,
                                           tgt_labels, tgt_points, out);
}